// round 7
// baseline (speedup 1.0000x reference)
#include <cuda_runtime.h>
#include <cuda_bf16.h>
#include <stdint.h>
#include <math.h>

// ---------------- problem constants ----------------
#define NPTS   100000
#define DIN    128
#define D2     64
#define DOUT   256
#define KPTS   15
#define SIGMA  0.04f
#define NEG    0.1f
#define EPSBN  1e-5f
#define CAP    96

// ---------------- scratch (device globals; no runtime alloc) ----------------
__device__ float  g_t  [(size_t)NPTS * D2];      // fp32 GEMM out (t, then y)
__device__ float  g_u2 [(size_t)NPTS * DOUT];
__device__ float  g_usc[(size_t)NPTS * DOUT];
__device__ __align__(16) __nv_bfloat16 g_xb [(size_t)NPTS * 2 * DIN];        // x split: [hi|lo]
__device__ __align__(16) __nv_bfloat16 g_yb [(size_t)NPTS * 2 * D2];         // ybn split
__device__ __align__(16) __nv_bfloat16 g_Sb [(size_t)NPTS * 2 * KPTS * D2];  // S split
__device__ __align__(16) __nv_bfloat16 g_w1b [D2   * 2 * DIN];   // Bt[n][2K]
__device__ __align__(16) __nv_bfloat16 g_wkpb[D2   * 2 * (KPTS*D2)];
__device__ __align__(16) __nv_bfloat16 g_w2b [DOUT * 2 * D2];
__device__ __align__(16) __nv_bfloat16 g_wscb[DOUT * 2 * DIN];
__device__ int    g_cnt[NPTS];
__device__ int    g_nbr[(size_t)NPTS * CAP];
__device__ double g_stats[1280];   // t:[0,128) y:[128,256) u2:[256,768) usc:[768,1280)
__device__ float2 g_bnp[640];      // (scale,shift): t:[0,64) y:[64,128) u2:[128,384) usc:[384,640)

// ---------------- small kernels ----------------
__global__ void zero_kernel() {
    int i = blockIdx.x * blockDim.x + threadIdx.x;
    if (i < NPTS) g_cnt[i] = 0;
    if (i < 1280) g_stats[i] = 0.0;
}

__global__ void scatter_kernel(const int* __restrict__ e_ref,
                               const int* __restrict__ e_qry, int E) {
    int e = blockIdx.x * blockDim.x + threadIdx.x;
    if (e >= E) return;
    int q = e_qry[e];
    int r = e_ref[e];
    int slot = atomicAdd(&g_cnt[q], 1);
    if (slot < CAP) g_nbr[(size_t)q * CAP + slot] = r;
}

__device__ __forceinline__ void bsplit(float v, __nv_bfloat16& h, __nv_bfloat16& l) {
    h = __float2bfloat16(v);
    l = __float2bfloat16(v - __bfloat162float(h));
}

__global__ void xsplit_kernel(const float* __restrict__ x, int n) {
    int i = blockIdx.x * blockDim.x + threadIdx.x;
    if (i >= n) return;
    int q = i / DIN, c = i % DIN;
    __nv_bfloat16 h, l;
    bsplit(x[i], h, l);
    g_xb[(size_t)q * 2 * DIN + c] = h;
    g_xb[(size_t)q * 2 * DIN + DIN + c] = l;
}

// W [K, N] fp32 -> out [N, 2K] bf16 (hi | lo)
__global__ void wsplit_kernel(const float* __restrict__ W, __nv_bfloat16* __restrict__ out,
                              int K, int N) {
    int i = blockIdx.x * blockDim.x + threadIdx.x;
    if (i >= K * N) return;
    int k = i / N, n = i % N;
    __nv_bfloat16 h, l;
    bsplit(W[i], h, l);
    out[(size_t)n * 2 * K + k] = h;
    out[(size_t)n * 2 * K + K + k] = l;
}

__global__ void bn_prep(int statOff, int C, const float* __restrict__ g,
                        const float* __restrict__ b, int prepOff, int M) {
    int i = threadIdx.x;
    if (i >= C) return;
    double m = g_stats[statOff + i] / (double)M;
    double v = g_stats[statOff + C + i] / (double)M - m * m;
    float rstd = rsqrtf((float)v + EPSBN);
    float scale = g[i] * rstd;
    float shift = b[i] - (float)m * scale;
    g_bnp[prepOff + i] = make_float2(scale, shift);
}

// BN + leaky, split bf16 out (feeds u2 GEMM), C=64
__global__ void bn_apply_ysplit(const float* __restrict__ in, int prepOff, int n) {
    int i = blockIdx.x * blockDim.x + threadIdx.x;
    if (i >= n) return;
    int c = i & 63, q = i >> 6;
    float2 p = __ldg(&g_bnp[prepOff + c]);
    float u = fmaf(in[i], p.x, p.y);
    u = (u >= 0.f) ? u : NEG * u;
    __nv_bfloat16 h, l;
    bsplit(u, h, l);
    g_yb[(size_t)q * 128 + c] = h;
    g_yb[(size_t)q * 128 + 64 + c] = l;
}

// ---------------- S build: one warp per query, high-MLP, fused BN+leaky ----------------
// Reads raw t (pre-BN); applies per-channel scale/shift + leaky inline.
// lane owns channels (2*lane, 2*lane+1); writes split bf16 S.
__global__ __launch_bounds__(256) void sbuild_kernel(
    const float* __restrict__ pos, const float* __restrict__ kp)
{
    __shared__ float skp[45];
    int tid = threadIdx.x;
    int lane = tid & 31;
    int warp = tid >> 5;
    if (tid < 45) skp[tid] = kp[tid];
    __syncthreads();

    int q = blockIdx.x * 8 + warp;
    if (q >= NPTS) return;

    float kx = 0.f, ky = 0.f, kz = 0.f;
    if (lane < KPTS) {
        kx = skp[lane * 3 + 0];
        ky = skp[lane * 3 + 1];
        kz = skp[lane * 3 + 2];
    }
    // BN params for this lane's two channels
    float2 p0 = __ldg(&g_bnp[2 * lane]);
    float2 p1 = __ldg(&g_bnp[2 * lane + 1]);

    float a0[KPTS], a1[KPTS];
#pragma unroll
    for (int k = 0; k < KPTS; ++k) { a0[k] = 0.f; a1[k] = 0.f; }

    float4 pq = __ldg((const float4*)pos + q);
    int cnt = g_cnt[q];
    if (cnt > CAP) cnt = CAP;
    const int* nb = g_nbr + (size_t)q * CAP;

    for (int base = 0; base < cnt; base += 16) {
        int nn = cnt - base;
        if (nn > 16) nn = 16;
        // lanes 0..15: parallel neighbor index + pos loads (MLP=16)
        int j = base + lane;
        bool vld = (lane < 16) && (j < cnt);
        int r = vld ? __ldg(&nb[j]) : 0;
        float4 pr = vld ? __ldg((const float4*)pos + r) : pq;
        float rx = pr.y - pq.y;
        float ry = pr.z - pq.z;
        float rz = pr.w - pq.w;

        // prefetch all h-gathers for this chunk (MLP=16)
        float2 hv[16];
#pragma unroll
        for (int jj = 0; jj < 16; ++jj) {
            int rj = __shfl_sync(0xffffffffu, r, jj);
            if (jj < nn)
                hv[jj] = __ldg((const float2*)g_t + (size_t)rj * 32 + lane);
        }

#pragma unroll
        for (int jj = 0; jj < 16; ++jj) {
            if (jj >= nn) break;
            float rxj = __shfl_sync(0xffffffffu, rx, jj);
            float ryj = __shfl_sync(0xffffffffu, ry, jj);
            float rzj = __shfl_sync(0xffffffffu, rz, jj);
            float infl = 0.f;
            if (lane < KPTS) {
                float dx = rxj - kx, dy = ryj - ky, dz = rzj - kz;
                float d2 = dx * dx + dy * dy + dz * dz;
                if (d2 < SIGMA * SIGMA)
                    infl = 1.f - sqrtf(d2) * (1.f / SIGMA);
            }
            unsigned m = __ballot_sync(0xffffffffu, infl > 0.f);
            if (!m) continue;
            // fused BN + leaky on the gathered raw t values
            float h0 = fmaf(hv[jj].x, p0.x, p0.y);
            h0 = (h0 >= 0.f) ? h0 : NEG * h0;
            float h1 = fmaf(hv[jj].y, p1.x, p1.y);
            h1 = (h1 >= 0.f) ? h1 : NEG * h1;
#pragma unroll
            for (int k = 0; k < KPTS; ++k) {
                if (m & (1u << k)) {
                    float w = __shfl_sync(0xffffffffu, infl, k);
                    a0[k] += w * h0;
                    a1[k] += w * h1;
                }
            }
        }
    }

    // split bf16: hi elems [0,960), lo [960,1920)
    __nv_bfloat162* Sout = (__nv_bfloat162*)(g_Sb + (size_t)q * 1920);
#pragma unroll
    for (int k = 0; k < KPTS; ++k) {
        __nv_bfloat16 h0, l0, h1, l1;
        bsplit(a0[k], h0, l0);
        bsplit(a1[k], h1, l1);
        __nv_bfloat162 hh; hh.x = h0; hh.y = h1;
        __nv_bfloat162 ll; ll.x = l0; ll.y = l1;
        Sout[k * 32 + lane] = hh;
        Sout[480 + k * 32 + lane] = ll;
    }
}

// ---------------- warp-MMA GEMM: C[M,Nc] = A @ B^T (split bf16, 3-term) ----------------
#define ROWP 72
#define A_SEC (128 * ROWP)
#define B_SEC (64 * ROWP)
#define GSMEM_BYTES ((2 * A_SEC + 2 * B_SEC) * 2 + 512)

__device__ __forceinline__ void mma16816(float* c, const uint32_t* a, const uint32_t* b) {
    asm volatile(
        "mma.sync.aligned.m16n8k16.row.col.f32.bf16.bf16.f32 "
        "{%0,%1,%2,%3}, {%4,%5,%6,%7}, {%8,%9}, {%0,%1,%2,%3};"
        : "+f"(c[0]), "+f"(c[1]), "+f"(c[2]), "+f"(c[3])
        : "r"(a[0]), "r"(a[1]), "r"(a[2]), "r"(a[3]), "r"(b[0]), "r"(b[1]));
}

__global__ __launch_bounds__(256) void gemm_mma(
    const __nv_bfloat16* __restrict__ A,
    const __nv_bfloat16* __restrict__ B,
    float* __restrict__ C,
    int M, int K, int Nc, int statOff, int statC)
{
    extern __shared__ char smem[];
    __nv_bfloat16* sA = (__nv_bfloat16*)smem;
    __nv_bfloat16* sB = sA + 2 * A_SEC;
    float* red = (float*)(smem + (2 * A_SEC + 2 * B_SEC) * 2);

    const int tid = threadIdx.x;
    const int lane = tid & 31;
    const int wid = tid >> 5;
    const int wm = wid & 3;
    const int wn = wid >> 2;
    const int g = lane >> 2;
    const int t = lane & 3;
    const int m0 = blockIdx.x * 128;
    const int n0 = blockIdx.y * 64;
    const int lda = 2 * K;
    const int nch = K >> 6;

    if (tid < 128) red[tid] = 0.f;

    float acc[2][4][4];
#pragma unroll
    for (int mi = 0; mi < 2; ++mi)
#pragma unroll
        for (int ni = 0; ni < 4; ++ni)
#pragma unroll
            for (int j = 0; j < 4; ++j) acc[mi][ni][j] = 0.f;

    for (int c = 0; c < nch; ++c) {
        int koh = c * 64;
#pragma unroll
        for (int i = 0; i < 4; ++i) {
            int idx = tid + 256 * i;
            int r = idx >> 3, cw = idx & 7;
            int gr = m0 + r;
            uint4 vh = make_uint4(0, 0, 0, 0), vl = vh;
            if (gr < M) {
                const uint4* base = (const uint4*)(A + (size_t)gr * lda);
                vh = __ldg(base + (koh >> 3) + cw);
                vl = __ldg(base + ((K + koh) >> 3) + cw);
            }
            *(uint4*)(sA + r * ROWP + cw * 8) = vh;
            *(uint4*)(sA + A_SEC + r * ROWP + cw * 8) = vl;
        }
#pragma unroll
        for (int i = 0; i < 2; ++i) {
            int idx = tid + 256 * i;
            int r = idx >> 3, cw = idx & 7;
            const uint4* base = (const uint4*)(B + (size_t)(n0 + r) * lda);
            uint4 vh = __ldg(base + (koh >> 3) + cw);
            uint4 vl = __ldg(base + ((K + koh) >> 3) + cw);
            *(uint4*)(sB + r * ROWP + cw * 8) = vh;
            *(uint4*)(sB + B_SEC + r * ROWP + cw * 8) = vl;
        }
        __syncthreads();

#pragma unroll
        for (int ks = 0; ks < 4; ++ks) {
            int col = ks * 16 + 2 * t;
            uint32_t ah[2][4], al[2][4];
#pragma unroll
            for (int mi = 0; mi < 2; ++mi) {
                const __nv_bfloat16* p = sA + (wm * 32 + mi * 16 + g) * ROWP + col;
                ah[mi][0] = *(const uint32_t*)p;
                ah[mi][1] = *(const uint32_t*)(p + 8 * ROWP);
                ah[mi][2] = *(const uint32_t*)(p + 8);
                ah[mi][3] = *(const uint32_t*)(p + 8 * ROWP + 8);
                const __nv_bfloat16* qp = p + A_SEC;
                al[mi][0] = *(const uint32_t*)qp;
                al[mi][1] = *(const uint32_t*)(qp + 8 * ROWP);
                al[mi][2] = *(const uint32_t*)(qp + 8);
                al[mi][3] = *(const uint32_t*)(qp + 8 * ROWP + 8);
            }
            uint32_t bh[4][2], bl[4][2];
#pragma unroll
            for (int ni = 0; ni < 4; ++ni) {
                const __nv_bfloat16* p = sB + (wn * 32 + ni * 8 + g) * ROWP + col;
                bh[ni][0] = *(const uint32_t*)p;
                bh[ni][1] = *(const uint32_t*)(p + 8);
                const __nv_bfloat16* qp = p + B_SEC;
                bl[ni][0] = *(const uint32_t*)qp;
                bl[ni][1] = *(const uint32_t*)(qp + 8);
            }
#pragma unroll
            for (int mi = 0; mi < 2; ++mi)
#pragma unroll
                for (int ni = 0; ni < 4; ++ni) {
                    mma16816(acc[mi][ni], ah[mi], bh[ni]);
                    mma16816(acc[mi][ni], ah[mi], bl[ni]);
                    mma16816(acc[mi][ni], al[mi], bh[ni]);
                }
        }
        __syncthreads();
    }

#pragma unroll
    for (int ni = 0; ni < 4; ++ni) {
        int colL = wn * 32 + ni * 8 + 2 * t;
        float s0 = 0.f, q0 = 0.f, s1 = 0.f, q1 = 0.f;
#pragma unroll
        for (int mi = 0; mi < 2; ++mi) {
            float* f = acc[mi][ni];
            int row = m0 + wm * 32 + mi * 16 + g;
            if (row < M) {
                C[(size_t)row * Nc + n0 + colL] = f[0];
                C[(size_t)row * Nc + n0 + colL + 1] = f[1];
                s0 += f[0]; q0 += f[0] * f[0];
                s1 += f[1]; q1 += f[1] * f[1];
            }
            if (row + 8 < M) {
                C[(size_t)(row + 8) * Nc + n0 + colL] = f[2];
                C[(size_t)(row + 8) * Nc + n0 + colL + 1] = f[3];
                s0 += f[2]; q0 += f[2] * f[2];
                s1 += f[3]; q1 += f[3] * f[3];
            }
        }
#pragma unroll
        for (int off = 4; off < 32; off <<= 1) {
            s0 += __shfl_xor_sync(0xffffffffu, s0, off);
            q0 += __shfl_xor_sync(0xffffffffu, q0, off);
            s1 += __shfl_xor_sync(0xffffffffu, s1, off);
            q1 += __shfl_xor_sync(0xffffffffu, q1, off);
        }
        if (g == 0) {
            atomicAdd(&red[colL], s0);
            atomicAdd(&red[64 + colL], q0);
            atomicAdd(&red[colL + 1], s1);
            atomicAdd(&red[64 + colL + 1], q1);
        }
    }
    __syncthreads();
    if (tid < 64) {
        atomicAdd(&g_stats[statOff + n0 + tid], (double)red[tid]);
        atomicAdd(&g_stats[statOff + statC + n0 + tid], (double)red[64 + tid]);
    }
}

// ---------------- final: out = leaky(bn(u2)) + bn(usc), float4 ----------------
__global__ void final_kernel(float4* __restrict__ out, int n4) {
    int i = blockIdx.x * blockDim.x + threadIdx.x;
    if (i >= n4) return;
    int c4 = (i & 63) * 4;
    float4 a = __ldg((const float4*)g_u2 + i);
    float4 s = __ldg((const float4*)g_usc + i);
    float4 o;
#pragma unroll
    for (int j = 0; j < 4; ++j) {
        float2 p2 = __ldg(&g_bnp[128 + c4 + j]);
        float2 ps = __ldg(&g_bnp[384 + c4 + j]);
        float u = fmaf((&a.x)[j], p2.x, p2.y);
        u = (u >= 0.f) ? u : NEG * u;
        (&o.x)[j] = u + fmaf((&s.x)[j], ps.x, ps.y);
    }
    out[i] = o;
}

// ---------------- launch ----------------
extern "C" void kernel_launch(void* const* d_in, const int* in_sizes, int n_in,
                              void* d_out, int out_size) {
    const float* pos    = (const float*)d_in[0];
    const float* x      = (const float*)d_in[1];
    const int*   e_ref  = (const int*)  d_in[2];
    const int*   e_qry  = (const int*)  d_in[3];
    const float* W1     = (const float*)d_in[4];
    const float* g1     = (const float*)d_in[5];
    const float* b1     = (const float*)d_in[6];
    const float* kp     = (const float*)d_in[7];
    const float* Wkp    = (const float*)d_in[8];
    const float* gkp    = (const float*)d_in[9];
    const float* bkp    = (const float*)d_in[10];
    const float* W2     = (const float*)d_in[11];
    const float* g2     = (const float*)d_in[12];
    const float* b2     = (const float*)d_in[13];
    const float* Wsc    = (const float*)d_in[14];
    const float* gsc    = (const float*)d_in[15];
    const float* bsc    = (const float*)d_in[16];
    float* out = (float*)d_out;

    const int M = NPTS;
    const int E = in_sizes[2];

    float *t_p, *u2_p, *usc_p;
    __nv_bfloat16 *xb_p, *yb_p, *Sb_p, *w1b_p, *wkpb_p, *w2b_p, *wscb_p;
    cudaGetSymbolAddress((void**)&t_p,    g_t);
    cudaGetSymbolAddress((void**)&u2_p,   g_u2);
    cudaGetSymbolAddress((void**)&usc_p,  g_usc);
    cudaGetSymbolAddress((void**)&xb_p,   g_xb);
    cudaGetSymbolAddress((void**)&yb_p,   g_yb);
    cudaGetSymbolAddress((void**)&Sb_p,   g_Sb);
    cudaGetSymbolAddress((void**)&w1b_p,  g_w1b);
    cudaGetSymbolAddress((void**)&wkpb_p, g_wkpb);
    cudaGetSymbolAddress((void**)&w2b_p,  g_w2b);
    cudaGetSymbolAddress((void**)&wscb_p, g_wscb);

    cudaFuncSetAttribute(gemm_mma, cudaFuncAttributeMaxDynamicSharedMemorySize, GSMEM_BYTES);

    // 0. zero counters + stats; bin edges
    zero_kernel<<<(NPTS + 255) / 256, 256>>>();
    scatter_kernel<<<(E + 255) / 256, 256>>>(e_ref, e_qry, E);

    // conversions
    xsplit_kernel<<<(M * DIN + 255) / 256, 256>>>(x, M * DIN);
    wsplit_kernel<<<(DIN * D2 + 255) / 256, 256>>>(W1, w1b_p, DIN, D2);
    wsplit_kernel<<<(KPTS * D2 * D2 + 255) / 256, 256>>>(Wkp, wkpb_p, KPTS * D2, D2);
    wsplit_kernel<<<(D2 * DOUT + 255) / 256, 256>>>(W2, w2b_p, D2, DOUT);
    wsplit_kernel<<<(DIN * DOUT + 255) / 256, 256>>>(Wsc, wscb_p, DIN, DOUT);

    const int MB = (M + 127) / 128;
    int n4_256 = M * DOUT / 4;

    // 1. t = x @ W1   (K=128, Nc=64, stats @0)
    gemm_mma<<<dim3(MB, 1), 256, GSMEM_BYTES>>>(xb_p, w1b_p, t_p, M, DIN, D2, 0, D2);
    // 2. BN params for t
    bn_prep<<<1, 64>>>(0, D2, g1, b1, 0, M);
    // 3. build split-bf16 S (fused BN+leaky on gathered t)
    sbuild_kernel<<<(M + 7) / 8, 256>>>(pos, kp);
    // 4. y = S @ Wkp  (K=960, Nc=64, stats @128) -> g_t
    gemm_mma<<<dim3(MB, 1), 256, GSMEM_BYTES>>>(Sb_p, wkpb_p, t_p, M, KPTS * D2, D2, 128, D2);
    // 5. ybn = leaky(bn(y)) -> split bf16
    bn_prep<<<1, 64>>>(128, D2, gkp, bkp, 64, M);
    bn_apply_ysplit<<<(M * D2 + 255) / 256, 256>>>(t_p, 64, M * D2);
    // 6. u2 = ybn @ W2  (K=64, Nc=256, stats @256)
    gemm_mma<<<dim3(MB, 4), 256, GSMEM_BYTES>>>(yb_p, w2b_p, u2_p, M, D2, DOUT, 256, DOUT);
    // 7. usc = x @ Wsc  (K=128, Nc=256, stats @768)
    gemm_mma<<<dim3(MB, 4), 256, GSMEM_BYTES>>>(xb_p, wscb_p, usc_p, M, DIN, DOUT, 768, DOUT);
    // 8. output
    bn_prep<<<1, 256>>>(256, DOUT, g2, b2, 128, M);
    bn_prep<<<1, 256>>>(768, DOUT, gsc, bsc, 384, M);
    final_kernel<<<(n4_256 + 255) / 256, 256>>>((float4*)out, n4_256);
}

// round 8
// speedup vs baseline: 1.4120x; 1.4120x over previous
#include <cuda_runtime.h>
#include <cuda_bf16.h>
#include <stdint.h>
#include <math.h>

// ---------------- problem constants ----------------
#define NPTS   100000
#define DIN    128
#define D2     64
#define DOUT   256
#define KPTS   15
#define SIGMA  0.04f
#define NEG    0.1f
#define EPSBN  1e-5f
#define CAP    96

// ---------------- scratch (device globals; no runtime alloc) ----------------
__device__ float  g_t  [(size_t)NPTS * D2];      // fp32 GEMM out (t, then y)
__device__ float  g_u2 [(size_t)NPTS * DOUT];
__device__ float  g_usc[(size_t)NPTS * DOUT];
__device__ __align__(16) __nv_bfloat16 g_xb [(size_t)NPTS * 2 * DIN];        // x split: [hi|lo]
__device__ __align__(16) __nv_bfloat16 g_yb [(size_t)NPTS * 2 * D2];         // ybn split
__device__ __align__(16) __nv_bfloat16 g_Sb [(size_t)NPTS * 2 * KPTS * D2];  // S split
__device__ __align__(16) __nv_bfloat16 g_w1b [D2   * 2 * DIN];   // Bt[n][2K]
__device__ __align__(16) __nv_bfloat16 g_wkpb[D2   * 2 * (KPTS*D2)];
__device__ __align__(16) __nv_bfloat16 g_w2b [DOUT * 2 * D2];
__device__ __align__(16) __nv_bfloat16 g_wscb[DOUT * 2 * DIN];
__device__ int    g_cnt[NPTS];
__device__ int    g_nbr[(size_t)NPTS * CAP];
__device__ double g_stats[1280];   // t:[0,128) y:[128,256) u2:[256,768) usc:[768,1280)
__device__ float2 g_bnp[640];      // (scale,shift): t:[0,64) y:[64,128) u2:[128,384) usc:[384,640)

// ---------------- small kernels ----------------
__global__ void zero_kernel() {
    int i = blockIdx.x * blockDim.x + threadIdx.x;
    if (i < NPTS) g_cnt[i] = 0;
    if (i < 1280) g_stats[i] = 0.0;
}

__global__ void scatter_kernel(const int* __restrict__ e_ref,
                               const int* __restrict__ e_qry, int E) {
    int e = blockIdx.x * blockDim.x + threadIdx.x;
    if (e >= E) return;
    int q = e_qry[e];
    int r = e_ref[e];
    int slot = atomicAdd(&g_cnt[q], 1);
    if (slot < CAP) g_nbr[(size_t)q * CAP + slot] = r;
}

__device__ __forceinline__ void bsplit(float v, __nv_bfloat16& h, __nv_bfloat16& l) {
    h = __float2bfloat16(v);
    l = __float2bfloat16(v - __bfloat162float(h));
}

__global__ void xsplit_kernel(const float* __restrict__ x, int n) {
    int i = blockIdx.x * blockDim.x + threadIdx.x;
    if (i >= n) return;
    int q = i / DIN, c = i % DIN;
    __nv_bfloat16 h, l;
    bsplit(x[i], h, l);
    g_xb[(size_t)q * 2 * DIN + c] = h;
    g_xb[(size_t)q * 2 * DIN + DIN + c] = l;
}

// W [K, N] fp32 -> out [N, 2K] bf16 (hi | lo)
__global__ void wsplit_kernel(const float* __restrict__ W, __nv_bfloat16* __restrict__ out,
                              int K, int N) {
    int i = blockIdx.x * blockDim.x + threadIdx.x;
    if (i >= K * N) return;
    int k = i / N, n = i % N;
    __nv_bfloat16 h, l;
    bsplit(W[i], h, l);
    out[(size_t)n * 2 * K + k] = h;
    out[(size_t)n * 2 * K + K + k] = l;
}

__global__ void bn_prep(int statOff, int C, const float* __restrict__ g,
                        const float* __restrict__ b, int prepOff, int M) {
    int i = threadIdx.x;
    if (i >= C) return;
    double m = g_stats[statOff + i] / (double)M;
    double v = g_stats[statOff + C + i] / (double)M - m * m;
    float rstd = rsqrtf((float)v + EPSBN);
    float scale = g[i] * rstd;
    float shift = b[i] - (float)m * scale;
    g_bnp[prepOff + i] = make_float2(scale, shift);
}

// BN + leaky, split bf16 out (feeds u2 GEMM), C=64
__global__ void bn_apply_ysplit(const float* __restrict__ in, int prepOff, int n) {
    int i = blockIdx.x * blockDim.x + threadIdx.x;
    if (i >= n) return;
    int c = i & 63, q = i >> 6;
    float2 p = __ldg(&g_bnp[prepOff + c]);
    float u = fmaf(in[i], p.x, p.y);
    u = (u >= 0.f) ? u : NEG * u;
    __nv_bfloat16 h, l;
    bsplit(u, h, l);
    g_yb[(size_t)q * 128 + c] = h;
    g_yb[(size_t)q * 128 + 64 + c] = l;
}

// ---------------- S build: one warp per query, depth-4 gather ring, fused BN+leaky ----------------
// Reads raw t (pre-BN); applies per-channel scale/shift + leaky inline.
// lane owns channels (2*lane, 2*lane+1); writes split bf16 S.
__global__ __launch_bounds__(256) void sbuild_kernel(
    const float* __restrict__ pos, const float* __restrict__ kp)
{
    __shared__ float skp[45];
    int tid = threadIdx.x;
    int lane = tid & 31;
    int warp = tid >> 5;
    if (tid < 45) skp[tid] = kp[tid];
    __syncthreads();

    int q = blockIdx.x * 8 + warp;
    if (q >= NPTS) return;

    float kx = 0.f, ky = 0.f, kz = 0.f;
    if (lane < KPTS) {
        kx = skp[lane * 3 + 0];
        ky = skp[lane * 3 + 1];
        kz = skp[lane * 3 + 2];
    }
    float2 p0 = __ldg(&g_bnp[2 * lane]);
    float2 p1 = __ldg(&g_bnp[2 * lane + 1]);

    float a0[KPTS], a1[KPTS];
#pragma unroll
    for (int k = 0; k < KPTS; ++k) { a0[k] = 0.f; a1[k] = 0.f; }

    float4 pq = __ldg((const float4*)pos + q);
    int cnt = g_cnt[q];
    if (cnt > CAP) cnt = CAP;
    const int* nb = g_nbr + (size_t)q * CAP;

    for (int base = 0; base < cnt; base += 16) {
        int nn = cnt - base;
        if (nn > 16) nn = 16;
        // lanes 0..15: parallel neighbor index + pos loads
        int j = base + lane;
        bool vld = (lane < 16) && (j < cnt);
        int r = vld ? __ldg(&nb[j]) : 0;
        float4 pr = vld ? __ldg((const float4*)pos + r) : pq;
        float rx = pr.y - pq.y;
        float ry = pr.z - pq.z;
        float rz = pr.w - pq.w;

        // depth-4 gather ring (bounded MLP; no spills)
        float2 hv[4];
#pragma unroll
        for (int p = 0; p < 4; ++p) {
            int rp = __shfl_sync(0xffffffffu, r, p);
            if (p < nn)
                hv[p] = __ldg((const float2*)g_t + (size_t)rp * 32 + lane);
        }

#pragma unroll
        for (int jj = 0; jj < 16; ++jj) {
            if (jj >= nn) break;
            float2 h2 = hv[jj & 3];
            {   // refill this ring slot with neighbor jj+4
                int rn = __shfl_sync(0xffffffffu, r, (jj + 4) & 15);
                if (jj + 4 < nn)
                    hv[jj & 3] = __ldg((const float2*)g_t + (size_t)rn * 32 + lane);
            }
            float rxj = __shfl_sync(0xffffffffu, rx, jj);
            float ryj = __shfl_sync(0xffffffffu, ry, jj);
            float rzj = __shfl_sync(0xffffffffu, rz, jj);
            float infl = 0.f;
            if (lane < KPTS) {
                float dx = rxj - kx, dy = ryj - ky, dz = rzj - kz;
                float d2 = dx * dx + dy * dy + dz * dz;
                if (d2 < SIGMA * SIGMA)
                    infl = 1.f - sqrtf(d2) * (1.f / SIGMA);
            }
            unsigned m = __ballot_sync(0xffffffffu, infl > 0.f);
            if (!m) continue;
            // fused BN + leaky on gathered raw t values
            float h0 = fmaf(h2.x, p0.x, p0.y);
            h0 = (h0 >= 0.f) ? h0 : NEG * h0;
            float h1 = fmaf(h2.y, p1.x, p1.y);
            h1 = (h1 >= 0.f) ? h1 : NEG * h1;
#pragma unroll
            for (int k = 0; k < KPTS; ++k) {
                if (m & (1u << k)) {
                    float w = __shfl_sync(0xffffffffu, infl, k);
                    a0[k] += w * h0;
                    a1[k] += w * h1;
                }
            }
        }
    }

    // split bf16: hi elems [0,960), lo [960,1920)
    __nv_bfloat162* Sout = (__nv_bfloat162*)(g_Sb + (size_t)q * 1920);
#pragma unroll
    for (int k = 0; k < KPTS; ++k) {
        __nv_bfloat16 h0, l0, h1, l1;
        bsplit(a0[k], h0, l0);
        bsplit(a1[k], h1, l1);
        __nv_bfloat162 hh; hh.x = h0; hh.y = h1;
        __nv_bfloat162 ll; ll.x = l0; ll.y = l1;
        Sout[k * 32 + lane] = hh;
        Sout[480 + k * 32 + lane] = ll;
    }
}

// ---------------- warp-MMA GEMM: C[M,Nc] = A @ B^T (split bf16, 3-term) ----------------
#define ROWP 72
#define A_SEC (128 * ROWP)
#define B_SEC (64 * ROWP)
#define GSMEM_BYTES ((2 * A_SEC + 2 * B_SEC) * 2 + 512)

__device__ __forceinline__ void mma16816(float* c, const uint32_t* a, const uint32_t* b) {
    asm volatile(
        "mma.sync.aligned.m16n8k16.row.col.f32.bf16.bf16.f32 "
        "{%0,%1,%2,%3}, {%4,%5,%6,%7}, {%8,%9}, {%0,%1,%2,%3};"
        : "+f"(c[0]), "+f"(c[1]), "+f"(c[2]), "+f"(c[3])
        : "r"(a[0]), "r"(a[1]), "r"(a[2]), "r"(a[3]), "r"(b[0]), "r"(b[1]));
}

__global__ __launch_bounds__(256) void gemm_mma(
    const __nv_bfloat16* __restrict__ A,
    const __nv_bfloat16* __restrict__ B,
    float* __restrict__ C,
    int M, int K, int Nc, int statOff, int statC)
{
    extern __shared__ char smem[];
    __nv_bfloat16* sA = (__nv_bfloat16*)smem;
    __nv_bfloat16* sB = sA + 2 * A_SEC;
    float* red = (float*)(smem + (2 * A_SEC + 2 * B_SEC) * 2);

    const int tid = threadIdx.x;
    const int lane = tid & 31;
    const int wid = tid >> 5;
    const int wm = wid & 3;
    const int wn = wid >> 2;
    const int g = lane >> 2;
    const int t = lane & 3;
    const int m0 = blockIdx.x * 128;
    const int n0 = blockIdx.y * 64;
    const int lda = 2 * K;
    const int nch = K >> 6;

    if (tid < 128) red[tid] = 0.f;

    float acc[2][4][4];
#pragma unroll
    for (int mi = 0; mi < 2; ++mi)
#pragma unroll
        for (int ni = 0; ni < 4; ++ni)
#pragma unroll
            for (int j = 0; j < 4; ++j) acc[mi][ni][j] = 0.f;

    for (int c = 0; c < nch; ++c) {
        int koh = c * 64;
#pragma unroll
        for (int i = 0; i < 4; ++i) {
            int idx = tid + 256 * i;
            int r = idx >> 3, cw = idx & 7;
            int gr = m0 + r;
            uint4 vh = make_uint4(0, 0, 0, 0), vl = vh;
            if (gr < M) {
                const uint4* base = (const uint4*)(A + (size_t)gr * lda);
                vh = __ldg(base + (koh >> 3) + cw);
                vl = __ldg(base + ((K + koh) >> 3) + cw);
            }
            *(uint4*)(sA + r * ROWP + cw * 8) = vh;
            *(uint4*)(sA + A_SEC + r * ROWP + cw * 8) = vl;
        }
#pragma unroll
        for (int i = 0; i < 2; ++i) {
            int idx = tid + 256 * i;
            int r = idx >> 3, cw = idx & 7;
            const uint4* base = (const uint4*)(B + (size_t)(n0 + r) * lda);
            uint4 vh = __ldg(base + (koh >> 3) + cw);
            uint4 vl = __ldg(base + ((K + koh) >> 3) + cw);
            *(uint4*)(sB + r * ROWP + cw * 8) = vh;
            *(uint4*)(sB + B_SEC + r * ROWP + cw * 8) = vl;
        }
        __syncthreads();

#pragma unroll
        for (int ks = 0; ks < 4; ++ks) {
            int col = ks * 16 + 2 * t;
            uint32_t ah[2][4], al[2][4];
#pragma unroll
            for (int mi = 0; mi < 2; ++mi) {
                const __nv_bfloat16* p = sA + (wm * 32 + mi * 16 + g) * ROWP + col;
                ah[mi][0] = *(const uint32_t*)p;
                ah[mi][1] = *(const uint32_t*)(p + 8 * ROWP);
                ah[mi][2] = *(const uint32_t*)(p + 8);
                ah[mi][3] = *(const uint32_t*)(p + 8 * ROWP + 8);
                const __nv_bfloat16* qp = p + A_SEC;
                al[mi][0] = *(const uint32_t*)qp;
                al[mi][1] = *(const uint32_t*)(qp + 8 * ROWP);
                al[mi][2] = *(const uint32_t*)(qp + 8);
                al[mi][3] = *(const uint32_t*)(qp + 8 * ROWP + 8);
            }
            uint32_t bh[4][2], bl[4][2];
#pragma unroll
            for (int ni = 0; ni < 4; ++ni) {
                const __nv_bfloat16* p = sB + (wn * 32 + ni * 8 + g) * ROWP + col;
                bh[ni][0] = *(const uint32_t*)p;
                bh[ni][1] = *(const uint32_t*)(p + 8);
                const __nv_bfloat16* qp = p + B_SEC;
                bl[ni][0] = *(const uint32_t*)qp;
                bl[ni][1] = *(const uint32_t*)(qp + 8);
            }
#pragma unroll
            for (int mi = 0; mi < 2; ++mi)
#pragma unroll
                for (int ni = 0; ni < 4; ++ni) {
                    mma16816(acc[mi][ni], ah[mi], bh[ni]);
                    mma16816(acc[mi][ni], ah[mi], bl[ni]);
                    mma16816(acc[mi][ni], al[mi], bh[ni]);
                }
        }
        __syncthreads();
    }

#pragma unroll
    for (int ni = 0; ni < 4; ++ni) {
        int colL = wn * 32 + ni * 8 + 2 * t;
        float s0 = 0.f, q0 = 0.f, s1 = 0.f, q1 = 0.f;
#pragma unroll
        for (int mi = 0; mi < 2; ++mi) {
            float* f = acc[mi][ni];
            int row = m0 + wm * 32 + mi * 16 + g;
            if (row < M) {
                C[(size_t)row * Nc + n0 + colL] = f[0];
                C[(size_t)row * Nc + n0 + colL + 1] = f[1];
                s0 += f[0]; q0 += f[0] * f[0];
                s1 += f[1]; q1 += f[1] * f[1];
            }
            if (row + 8 < M) {
                C[(size_t)(row + 8) * Nc + n0 + colL] = f[2];
                C[(size_t)(row + 8) * Nc + n0 + colL + 1] = f[3];
                s0 += f[2]; q0 += f[2] * f[2];
                s1 += f[3]; q1 += f[3] * f[3];
            }
        }
#pragma unroll
        for (int off = 4; off < 32; off <<= 1) {
            s0 += __shfl_xor_sync(0xffffffffu, s0, off);
            q0 += __shfl_xor_sync(0xffffffffu, q0, off);
            s1 += __shfl_xor_sync(0xffffffffu, s1, off);
            q1 += __shfl_xor_sync(0xffffffffu, q1, off);
        }
        if (g == 0) {
            atomicAdd(&red[colL], s0);
            atomicAdd(&red[64 + colL], q0);
            atomicAdd(&red[colL + 1], s1);
            atomicAdd(&red[64 + colL + 1], q1);
        }
    }
    __syncthreads();
    if (tid < 64) {
        atomicAdd(&g_stats[statOff + n0 + tid], (double)red[tid]);
        atomicAdd(&g_stats[statOff + statC + n0 + tid], (double)red[64 + tid]);
    }
}

// ---------------- final: out = leaky(bn(u2)) + bn(usc), float4 ----------------
__global__ void final_kernel(float4* __restrict__ out, int n4) {
    int i = blockIdx.x * blockDim.x + threadIdx.x;
    if (i >= n4) return;
    int c4 = (i & 63) * 4;
    float4 a = __ldg((const float4*)g_u2 + i);
    float4 s = __ldg((const float4*)g_usc + i);
    float4 o;
#pragma unroll
    for (int j = 0; j < 4; ++j) {
        float2 p2 = __ldg(&g_bnp[128 + c4 + j]);
        float2 ps = __ldg(&g_bnp[384 + c4 + j]);
        float u = fmaf((&a.x)[j], p2.x, p2.y);
        u = (u >= 0.f) ? u : NEG * u;
        (&o.x)[j] = u + fmaf((&s.x)[j], ps.x, ps.y);
    }
    out[i] = o;
}

// ---------------- launch ----------------
extern "C" void kernel_launch(void* const* d_in, const int* in_sizes, int n_in,
                              void* d_out, int out_size) {
    const float* pos    = (const float*)d_in[0];
    const float* x      = (const float*)d_in[1];
    const int*   e_ref  = (const int*)  d_in[2];
    const int*   e_qry  = (const int*)  d_in[3];
    const float* W1     = (const float*)d_in[4];
    const float* g1     = (const float*)d_in[5];
    const float* b1     = (const float*)d_in[6];
    const float* kp     = (const float*)d_in[7];
    const float* Wkp    = (const float*)d_in[8];
    const float* gkp    = (const float*)d_in[9];
    const float* bkp    = (const float*)d_in[10];
    const float* W2     = (const float*)d_in[11];
    const float* g2     = (const float*)d_in[12];
    const float* b2     = (const float*)d_in[13];
    const float* Wsc    = (const float*)d_in[14];
    const float* gsc    = (const float*)d_in[15];
    const float* bsc    = (const float*)d_in[16];
    float* out = (float*)d_out;

    const int M = NPTS;
    const int E = in_sizes[2];

    float *t_p, *u2_p, *usc_p;
    __nv_bfloat16 *xb_p, *yb_p, *Sb_p, *w1b_p, *wkpb_p, *w2b_p, *wscb_p;
    cudaGetSymbolAddress((void**)&t_p,    g_t);
    cudaGetSymbolAddress((void**)&u2_p,   g_u2);
    cudaGetSymbolAddress((void**)&usc_p,  g_usc);
    cudaGetSymbolAddress((void**)&xb_p,   g_xb);
    cudaGetSymbolAddress((void**)&yb_p,   g_yb);
    cudaGetSymbolAddress((void**)&Sb_p,   g_Sb);
    cudaGetSymbolAddress((void**)&w1b_p,  g_w1b);
    cudaGetSymbolAddress((void**)&wkpb_p, g_wkpb);
    cudaGetSymbolAddress((void**)&w2b_p,  g_w2b);
    cudaGetSymbolAddress((void**)&wscb_p, g_wscb);

    cudaFuncSetAttribute(gemm_mma, cudaFuncAttributeMaxDynamicSharedMemorySize, GSMEM_BYTES);

    // 0. zero counters + stats; bin edges
    zero_kernel<<<(NPTS + 255) / 256, 256>>>();
    scatter_kernel<<<(E + 255) / 256, 256>>>(e_ref, e_qry, E);

    // conversions
    xsplit_kernel<<<(M * DIN + 255) / 256, 256>>>(x, M * DIN);
    wsplit_kernel<<<(DIN * D2 + 255) / 256, 256>>>(W1, w1b_p, DIN, D2);
    wsplit_kernel<<<(KPTS * D2 * D2 + 255) / 256, 256>>>(Wkp, wkpb_p, KPTS * D2, D2);
    wsplit_kernel<<<(D2 * DOUT + 255) / 256, 256>>>(W2, w2b_p, D2, DOUT);
    wsplit_kernel<<<(DIN * DOUT + 255) / 256, 256>>>(Wsc, wscb_p, DIN, DOUT);

    const int MB = (M + 127) / 128;
    int n4_256 = M * DOUT / 4;

    // 1. t = x @ W1   (K=128, Nc=64, stats @0)
    gemm_mma<<<dim3(MB, 1), 256, GSMEM_BYTES>>>(xb_p, w1b_p, t_p, M, DIN, D2, 0, D2);
    // 2. BN params for t
    bn_prep<<<1, 64>>>(0, D2, g1, b1, 0, M);
    // 3. build split-bf16 S (fused BN+leaky on gathered t, depth-4 ring)
    sbuild_kernel<<<(M + 7) / 8, 256>>>(pos, kp);
    // 4. y = S @ Wkp  (K=960, Nc=64, stats @128) -> g_t
    gemm_mma<<<dim3(MB, 1), 256, GSMEM_BYTES>>>(Sb_p, wkpb_p, t_p, M, KPTS * D2, D2, 128, D2);
    // 5. ybn = leaky(bn(y)) -> split bf16
    bn_prep<<<1, 64>>>(128, D2, gkp, bkp, 64, M);
    bn_apply_ysplit<<<(M * D2 + 255) / 256, 256>>>(t_p, 64, M * D2);
    // 6. u2 = ybn @ W2  (K=64, Nc=256, stats @256)
    gemm_mma<<<dim3(MB, 4), 256, GSMEM_BYTES>>>(yb_p, w2b_p, u2_p, M, D2, DOUT, 256, DOUT);
    // 7. usc = x @ Wsc  (K=128, Nc=256, stats @768)
    gemm_mma<<<dim3(MB, 4), 256, GSMEM_BYTES>>>(xb_p, wscb_p, usc_p, M, DIN, DOUT, 768, DOUT);
    // 8. output
    bn_prep<<<1, 256>>>(256, DOUT, g2, b2, 128, M);
    bn_prep<<<1, 256>>>(768, DOUT, gsc, bsc, 384, M);
    final_kernel<<<(n4_256 + 255) / 256, 256>>>((float4*)out, n4_256);
}

// round 9
// speedup vs baseline: 1.8040x; 1.2776x over previous
#include <cuda_runtime.h>
#include <cuda_bf16.h>
#include <stdint.h>
#include <math.h>

// ---------------- problem constants ----------------
#define NPTS   100000
#define DIN    128
#define D2     64
#define DOUT   256
#define KPTS   15
#define SIGMA  0.04f
#define NEG    0.1f
#define EPSBN  1e-5f
#define CAP    96

// ---------------- scratch (device globals; no runtime alloc) ----------------
__device__ float  g_t  [(size_t)NPTS * D2];      // fp32 GEMM out (t, then y)
__device__ float  g_u2 [(size_t)NPTS * DOUT];
__device__ float  g_usc[(size_t)NPTS * DOUT];
__device__ __align__(16) __nv_bfloat16 g_xb [(size_t)NPTS * 2 * DIN];        // x split: [hi|lo]
__device__ __align__(16) __nv_bfloat16 g_yb [(size_t)NPTS * 2 * D2];         // ybn split
__device__ __align__(16) __nv_bfloat16 g_Sb [(size_t)NPTS * 2 * KPTS * D2];  // S split
__device__ __align__(16) __nv_bfloat16 g_w1b [D2   * 2 * DIN];   // Bt[n][2K]
__device__ __align__(16) __nv_bfloat16 g_wkpb[D2   * 2 * (KPTS*D2)];
__device__ __align__(16) __nv_bfloat16 g_w2b [DOUT * 2 * D2];
__device__ __align__(16) __nv_bfloat16 g_wscb[DOUT * 2 * DIN];
__device__ int    g_cnt[NPTS];
__device__ int    g_nbr[(size_t)NPTS * CAP];
__device__ double g_stats[1280];   // t:[0,128) y:[128,256) u2:[256,768) usc:[768,1280)
__device__ float2 g_bnp[640];      // (scale,shift): t:[0,64) y:[64,128) u2:[128,384) usc:[384,640)

// ---------------- small kernels ----------------
__global__ void zero_kernel() {
    int i = blockIdx.x * blockDim.x + threadIdx.x;
    if (i < NPTS) g_cnt[i] = 0;
    if (i < 1280) g_stats[i] = 0.0;
}

__global__ void scatter_kernel(const int* __restrict__ e_ref,
                               const int* __restrict__ e_qry, int E) {
    int e = blockIdx.x * blockDim.x + threadIdx.x;
    if (e >= E) return;
    int q = e_qry[e];
    int r = e_ref[e];
    int slot = atomicAdd(&g_cnt[q], 1);
    if (slot < CAP) g_nbr[(size_t)q * CAP + slot] = r;
}

__device__ __forceinline__ void bsplit(float v, __nv_bfloat16& h, __nv_bfloat16& l) {
    h = __float2bfloat16(v);
    l = __float2bfloat16(v - __bfloat162float(h));
}

__global__ void xsplit_kernel(const float* __restrict__ x, int n) {
    int i = blockIdx.x * blockDim.x + threadIdx.x;
    if (i >= n) return;
    int q = i / DIN, c = i % DIN;
    __nv_bfloat16 h, l;
    bsplit(x[i], h, l);
    g_xb[(size_t)q * 2 * DIN + c] = h;
    g_xb[(size_t)q * 2 * DIN + DIN + c] = l;
}

// W [K, N] fp32 -> out [N, 2K] bf16 (hi | lo)
__global__ void wsplit_kernel(const float* __restrict__ W, __nv_bfloat16* __restrict__ out,
                              int K, int N) {
    int i = blockIdx.x * blockDim.x + threadIdx.x;
    if (i >= K * N) return;
    int k = i / N, n = i % N;
    __nv_bfloat16 h, l;
    bsplit(W[i], h, l);
    out[(size_t)n * 2 * K + k] = h;
    out[(size_t)n * 2 * K + K + k] = l;
}

__global__ void bn_prep(int statOff, int C, const float* __restrict__ g,
                        const float* __restrict__ b, int prepOff, int M) {
    int i = threadIdx.x;
    if (i >= C) return;
    double m = g_stats[statOff + i] / (double)M;
    double v = g_stats[statOff + C + i] / (double)M - m * m;
    float rstd = rsqrtf((float)v + EPSBN);
    float scale = g[i] * rstd;
    float shift = b[i] - (float)m * scale;
    g_bnp[prepOff + i] = make_float2(scale, shift);
}

// BN + leaky, split bf16 out (feeds u2 GEMM), C=64
__global__ void bn_apply_ysplit(const float* __restrict__ in, int prepOff, int n) {
    int i = blockIdx.x * blockDim.x + threadIdx.x;
    if (i >= n) return;
    int c = i & 63, q = i >> 6;
    float2 p = __ldg(&g_bnp[prepOff + c]);
    float u = fmaf(in[i], p.x, p.y);
    u = (u >= 0.f) ? u : NEG * u;
    __nv_bfloat16 h, l;
    bsplit(u, h, l);
    g_yb[(size_t)q * 128 + c] = h;
    g_yb[(size_t)q * 128 + 64 + c] = l;
}

// ---------------- S build: one warp per query (round-6 serial structure),
// with ONLY the BN+leaky fused into the gather (reads raw g_t). ----------------
__global__ __launch_bounds__(256) void sbuild_kernel(
    const float* __restrict__ pos, const float* __restrict__ kp)
{
    __shared__ float skp[45];
    int tid = threadIdx.x;
    int lane = tid & 31;
    int warp = tid >> 5;
    if (tid < 45) skp[tid] = kp[tid];
    __syncthreads();

    int q = blockIdx.x * 8 + warp;
    if (q >= NPTS) return;

    float kx = 0.f, ky = 0.f, kz = 0.f;
    if (lane < KPTS) {
        kx = skp[lane * 3 + 0];
        ky = skp[lane * 3 + 1];
        kz = skp[lane * 3 + 2];
    }
    // BN params for this lane's two channels (2*lane, 2*lane+1)
    float2 p0 = __ldg(&g_bnp[2 * lane]);
    float2 p1 = __ldg(&g_bnp[2 * lane + 1]);

    float a0[KPTS], a1[KPTS];
#pragma unroll
    for (int k = 0; k < KPTS; ++k) { a0[k] = 0.f; a1[k] = 0.f; }

    float4 pq = __ldg((const float4*)pos + q);
    int cnt = g_cnt[q];
    if (cnt > CAP) cnt = CAP;
    const int* nb = g_nbr + (size_t)q * CAP;

    for (int j = 0; j < cnt; ++j) {
        int r = __ldg(&nb[j]);
        float4 pr = __ldg((const float4*)pos + r);
        float rx = pr.y - pq.y;
        float ry = pr.z - pq.z;
        float rz = pr.w - pq.w;
        float infl = 0.f;
        if (lane < KPTS) {
            float dx = rx - kx, dy = ry - ky, dz = rz - kz;
            float d2 = dx * dx + dy * dy + dz * dz;
            if (d2 < SIGMA * SIGMA)
                infl = 1.f - sqrtf(d2) * (1.f / SIGMA);
        }
        unsigned m = __ballot_sync(0xffffffffu, infl > 0.f);
        if (!m) continue;
        float2 hv = __ldg((const float2*)g_t + (size_t)r * 32 + lane);
        // fused BN + leaky on the gathered raw t values
        float h0 = fmaf(hv.x, p0.x, p0.y);
        h0 = (h0 >= 0.f) ? h0 : NEG * h0;
        float h1 = fmaf(hv.y, p1.x, p1.y);
        h1 = (h1 >= 0.f) ? h1 : NEG * h1;
#pragma unroll
        for (int k = 0; k < KPTS; ++k) {
            if (m & (1u << k)) {
                float w = __shfl_sync(0xffffffffu, infl, k);
                a0[k] += w * h0;
                a1[k] += w * h1;
            }
        }
    }

    // split bf16: hi elems [0,960), lo [960,1920); lane owns channels 2lane,2lane+1
    __nv_bfloat162* Sout = (__nv_bfloat162*)(g_Sb + (size_t)q * 1920);
#pragma unroll
    for (int k = 0; k < KPTS; ++k) {
        __nv_bfloat16 h0, l0, h1, l1;
        bsplit(a0[k], h0, l0);
        bsplit(a1[k], h1, l1);
        __nv_bfloat162 hh; hh.x = h0; hh.y = h1;
        __nv_bfloat162 ll; ll.x = l0; ll.y = l1;
        Sout[k * 32 + lane] = hh;
        Sout[480 + k * 32 + lane] = ll;
    }
}

// ---------------- warp-MMA GEMM: C[M,Nc] = A @ B^T (split bf16, 3-term) ----------------
#define ROWP 72
#define A_SEC (128 * ROWP)
#define B_SEC (64 * ROWP)
#define GSMEM_BYTES ((2 * A_SEC + 2 * B_SEC) * 2 + 512)

__device__ __forceinline__ void mma16816(float* c, const uint32_t* a, const uint32_t* b) {
    asm volatile(
        "mma.sync.aligned.m16n8k16.row.col.f32.bf16.bf16.f32 "
        "{%0,%1,%2,%3}, {%4,%5,%6,%7}, {%8,%9}, {%0,%1,%2,%3};"
        : "+f"(c[0]), "+f"(c[1]), "+f"(c[2]), "+f"(c[3])
        : "r"(a[0]), "r"(a[1]), "r"(a[2]), "r"(a[3]), "r"(b[0]), "r"(b[1]));
}

__global__ __launch_bounds__(256) void gemm_mma(
    const __nv_bfloat16* __restrict__ A,
    const __nv_bfloat16* __restrict__ B,
    float* __restrict__ C,
    int M, int K, int Nc, int statOff, int statC)
{
    extern __shared__ char smem[];
    __nv_bfloat16* sA = (__nv_bfloat16*)smem;
    __nv_bfloat16* sB = sA + 2 * A_SEC;
    float* red = (float*)(smem + (2 * A_SEC + 2 * B_SEC) * 2);

    const int tid = threadIdx.x;
    const int lane = tid & 31;
    const int wid = tid >> 5;
    const int wm = wid & 3;
    const int wn = wid >> 2;
    const int g = lane >> 2;
    const int t = lane & 3;
    const int m0 = blockIdx.x * 128;
    const int n0 = blockIdx.y * 64;
    const int lda = 2 * K;
    const int nch = K >> 6;

    if (tid < 128) red[tid] = 0.f;

    float acc[2][4][4];
#pragma unroll
    for (int mi = 0; mi < 2; ++mi)
#pragma unroll
        for (int ni = 0; ni < 4; ++ni)
#pragma unroll
            for (int j = 0; j < 4; ++j) acc[mi][ni][j] = 0.f;

    for (int c = 0; c < nch; ++c) {
        int koh = c * 64;
#pragma unroll
        for (int i = 0; i < 4; ++i) {
            int idx = tid + 256 * i;
            int r = idx >> 3, cw = idx & 7;
            int gr = m0 + r;
            uint4 vh = make_uint4(0, 0, 0, 0), vl = vh;
            if (gr < M) {
                const uint4* base = (const uint4*)(A + (size_t)gr * lda);
                vh = __ldg(base + (koh >> 3) + cw);
                vl = __ldg(base + ((K + koh) >> 3) + cw);
            }
            *(uint4*)(sA + r * ROWP + cw * 8) = vh;
            *(uint4*)(sA + A_SEC + r * ROWP + cw * 8) = vl;
        }
#pragma unroll
        for (int i = 0; i < 2; ++i) {
            int idx = tid + 256 * i;
            int r = idx >> 3, cw = idx & 7;
            const uint4* base = (const uint4*)(B + (size_t)(n0 + r) * lda);
            uint4 vh = __ldg(base + (koh >> 3) + cw);
            uint4 vl = __ldg(base + ((K + koh) >> 3) + cw);
            *(uint4*)(sB + r * ROWP + cw * 8) = vh;
            *(uint4*)(sB + B_SEC + r * ROWP + cw * 8) = vl;
        }
        __syncthreads();

#pragma unroll
        for (int ks = 0; ks < 4; ++ks) {
            int col = ks * 16 + 2 * t;
            uint32_t ah[2][4], al[2][4];
#pragma unroll
            for (int mi = 0; mi < 2; ++mi) {
                const __nv_bfloat16* p = sA + (wm * 32 + mi * 16 + g) * ROWP + col;
                ah[mi][0] = *(const uint32_t*)p;
                ah[mi][1] = *(const uint32_t*)(p + 8 * ROWP);
                ah[mi][2] = *(const uint32_t*)(p + 8);
                ah[mi][3] = *(const uint32_t*)(p + 8 * ROWP + 8);
                const __nv_bfloat16* qp = p + A_SEC;
                al[mi][0] = *(const uint32_t*)qp;
                al[mi][1] = *(const uint32_t*)(qp + 8 * ROWP);
                al[mi][2] = *(const uint32_t*)(qp + 8);
                al[mi][3] = *(const uint32_t*)(qp + 8 * ROWP + 8);
            }
            uint32_t bh[4][2], bl[4][2];
#pragma unroll
            for (int ni = 0; ni < 4; ++ni) {
                const __nv_bfloat16* p = sB + (wn * 32 + ni * 8 + g) * ROWP + col;
                bh[ni][0] = *(const uint32_t*)p;
                bh[ni][1] = *(const uint32_t*)(p + 8);
                const __nv_bfloat16* qp = p + B_SEC;
                bl[ni][0] = *(const uint32_t*)qp;
                bl[ni][1] = *(const uint32_t*)(qp + 8);
            }
#pragma unroll
            for (int mi = 0; mi < 2; ++mi)
#pragma unroll
                for (int ni = 0; ni < 4; ++ni) {
                    mma16816(acc[mi][ni], ah[mi], bh[ni]);
                    mma16816(acc[mi][ni], ah[mi], bl[ni]);
                    mma16816(acc[mi][ni], al[mi], bh[ni]);
                }
        }
        __syncthreads();
    }

#pragma unroll
    for (int ni = 0; ni < 4; ++ni) {
        int colL = wn * 32 + ni * 8 + 2 * t;
        float s0 = 0.f, q0 = 0.f, s1 = 0.f, q1 = 0.f;
#pragma unroll
        for (int mi = 0; mi < 2; ++mi) {
            float* f = acc[mi][ni];
            int row = m0 + wm * 32 + mi * 16 + g;
            if (row < M) {
                C[(size_t)row * Nc + n0 + colL] = f[0];
                C[(size_t)row * Nc + n0 + colL + 1] = f[1];
                s0 += f[0]; q0 += f[0] * f[0];
                s1 += f[1]; q1 += f[1] * f[1];
            }
            if (row + 8 < M) {
                C[(size_t)(row + 8) * Nc + n0 + colL] = f[2];
                C[(size_t)(row + 8) * Nc + n0 + colL + 1] = f[3];
                s0 += f[2]; q0 += f[2] * f[2];
                s1 += f[3]; q1 += f[3] * f[3];
            }
        }
#pragma unroll
        for (int off = 4; off < 32; off <<= 1) {
            s0 += __shfl_xor_sync(0xffffffffu, s0, off);
            q0 += __shfl_xor_sync(0xffffffffu, q0, off);
            s1 += __shfl_xor_sync(0xffffffffu, s1, off);
            q1 += __shfl_xor_sync(0xffffffffu, q1, off);
        }
        if (g == 0) {
            atomicAdd(&red[colL], s0);
            atomicAdd(&red[64 + colL], q0);
            atomicAdd(&red[colL + 1], s1);
            atomicAdd(&red[64 + colL + 1], q1);
        }
    }
    __syncthreads();
    if (tid < 64) {
        atomicAdd(&g_stats[statOff + n0 + tid], (double)red[tid]);
        atomicAdd(&g_stats[statOff + statC + n0 + tid], (double)red[64 + tid]);
    }
}

// ---------------- final: out = leaky(bn(u2)) + bn(usc), float4 ----------------
__global__ void final_kernel(float4* __restrict__ out, int n4) {
    int i = blockIdx.x * blockDim.x + threadIdx.x;
    if (i >= n4) return;
    int c4 = (i & 63) * 4;
    float4 a = __ldg((const float4*)g_u2 + i);
    float4 s = __ldg((const float4*)g_usc + i);
    float4 o;
#pragma unroll
    for (int j = 0; j < 4; ++j) {
        float2 p2 = __ldg(&g_bnp[128 + c4 + j]);
        float2 ps = __ldg(&g_bnp[384 + c4 + j]);
        float u = fmaf((&a.x)[j], p2.x, p2.y);
        u = (u >= 0.f) ? u : NEG * u;
        (&o.x)[j] = u + fmaf((&s.x)[j], ps.x, ps.y);
    }
    out[i] = o;
}

// ---------------- launch ----------------
extern "C" void kernel_launch(void* const* d_in, const int* in_sizes, int n_in,
                              void* d_out, int out_size) {
    const float* pos    = (const float*)d_in[0];
    const float* x      = (const float*)d_in[1];
    const int*   e_ref  = (const int*)  d_in[2];
    const int*   e_qry  = (const int*)  d_in[3];
    const float* W1     = (const float*)d_in[4];
    const float* g1     = (const float*)d_in[5];
    const float* b1     = (const float*)d_in[6];
    const float* kp     = (const float*)d_in[7];
    const float* Wkp    = (const float*)d_in[8];
    const float* gkp    = (const float*)d_in[9];
    const float* bkp    = (const float*)d_in[10];
    const float* W2     = (const float*)d_in[11];
    const float* g2     = (const float*)d_in[12];
    const float* b2     = (const float*)d_in[13];
    const float* Wsc    = (const float*)d_in[14];
    const float* gsc    = (const float*)d_in[15];
    const float* bsc    = (const float*)d_in[16];
    float* out = (float*)d_out;

    const int M = NPTS;
    const int E = in_sizes[2];

    float *t_p, *u2_p, *usc_p;
    __nv_bfloat16 *xb_p, *yb_p, *Sb_p, *w1b_p, *wkpb_p, *w2b_p, *wscb_p;
    cudaGetSymbolAddress((void**)&t_p,    g_t);
    cudaGetSymbolAddress((void**)&u2_p,   g_u2);
    cudaGetSymbolAddress((void**)&usc_p,  g_usc);
    cudaGetSymbolAddress((void**)&xb_p,   g_xb);
    cudaGetSymbolAddress((void**)&yb_p,   g_yb);
    cudaGetSymbolAddress((void**)&Sb_p,   g_Sb);
    cudaGetSymbolAddress((void**)&w1b_p,  g_w1b);
    cudaGetSymbolAddress((void**)&wkpb_p, g_wkpb);
    cudaGetSymbolAddress((void**)&w2b_p,  g_w2b);
    cudaGetSymbolAddress((void**)&wscb_p, g_wscb);

    cudaFuncSetAttribute(gemm_mma, cudaFuncAttributeMaxDynamicSharedMemorySize, GSMEM_BYTES);

    // 0. zero counters + stats; bin edges
    zero_kernel<<<(NPTS + 255) / 256, 256>>>();
    scatter_kernel<<<(E + 255) / 256, 256>>>(e_ref, e_qry, E);

    // conversions
    xsplit_kernel<<<(M * DIN + 255) / 256, 256>>>(x, M * DIN);
    wsplit_kernel<<<(DIN * D2 + 255) / 256, 256>>>(W1, w1b_p, DIN, D2);
    wsplit_kernel<<<(KPTS * D2 * D2 + 255) / 256, 256>>>(Wkp, wkpb_p, KPTS * D2, D2);
    wsplit_kernel<<<(D2 * DOUT + 255) / 256, 256>>>(W2, w2b_p, D2, DOUT);
    wsplit_kernel<<<(DIN * DOUT + 255) / 256, 256>>>(Wsc, wscb_p, DIN, DOUT);

    const int MB = (M + 127) / 128;
    int n4_256 = M * DOUT / 4;

    // 1. t = x @ W1   (K=128, Nc=64, stats @0)
    gemm_mma<<<dim3(MB, 1), 256, GSMEM_BYTES>>>(xb_p, w1b_p, t_p, M, DIN, D2, 0, D2);
    // 2. BN params for t
    bn_prep<<<1, 64>>>(0, D2, g1, b1, 0, M);
    // 3. build split-bf16 S (round-6 serial loop; BN+leaky fused into the gather)
    sbuild_kernel<<<(M + 7) / 8, 256>>>(pos, kp);
    // 4. y = S @ Wkp  (K=960, Nc=64, stats @128) -> g_t
    gemm_mma<<<dim3(MB, 1), 256, GSMEM_BYTES>>>(Sb_p, wkpb_p, t_p, M, KPTS * D2, D2, 128, D2);
    // 5. ybn = leaky(bn(y)) -> split bf16
    bn_prep<<<1, 64>>>(128, D2, gkp, bkp, 64, M);
    bn_apply_ysplit<<<(M * D2 + 255) / 256, 256>>>(t_p, 64, M * D2);
    // 6. u2 = ybn @ W2  (K=64, Nc=256, stats @256)
    gemm_mma<<<dim3(MB, 4), 256, GSMEM_BYTES>>>(yb_p, w2b_p, u2_p, M, D2, DOUT, 256, DOUT);
    // 7. usc = x @ Wsc  (K=128, Nc=256, stats @768)
    gemm_mma<<<dim3(MB, 4), 256, GSMEM_BYTES>>>(xb_p, wscb_p, usc_p, M, DIN, DOUT, 768, DOUT);
    // 8. output
    bn_prep<<<1, 256>>>(256, DOUT, g2, b2, 128, M);
    bn_prep<<<1, 256>>>(768, DOUT, gsc, bsc, 384, M);
    final_kernel<<<(n4_256 + 255) / 256, 256>>>((float4*)out, n4_256);
}

// round 10
// speedup vs baseline: 1.9529x; 1.0825x over previous
#include <cuda_runtime.h>
#include <cuda_bf16.h>
#include <stdint.h>
#include <math.h>

// ---------------- problem constants ----------------
#define NPTS   100000
#define DIN    128
#define D2     64
#define DOUT   256
#define KPTS   15
#define SIGMA  0.04f
#define NEG    0.1f
#define EPSBN  1e-5f
#define CAP    96

// ---------------- scratch (device globals; no runtime alloc) ----------------
__device__ float  g_t  [(size_t)NPTS * D2];      // fp32 GEMM out (t, then y)
__device__ float  g_u2 [(size_t)NPTS * DOUT];
__device__ float  g_usc[(size_t)NPTS * DOUT];
__device__ __align__(16) __nv_bfloat16 g_Sb [(size_t)NPTS * 2 * KPTS * D2];  // S split
__device__ __align__(16) __nv_bfloat16 g_w1b [D2   * 2 * DIN];   // Bt[n][2K]
__device__ __align__(16) __nv_bfloat16 g_wkpb[D2   * 2 * (KPTS*D2)];
__device__ __align__(16) __nv_bfloat16 g_w2b [DOUT * 2 * D2];
__device__ __align__(16) __nv_bfloat16 g_wscb[DOUT * 2 * DIN];
__device__ int    g_cnt[NPTS];
__device__ int    g_nbr[(size_t)NPTS * CAP];
__device__ double g_stats[1280];   // t:[0,128) y:[128,256) u2:[256,768) usc:[768,1280)
__device__ float2 g_bnp[640];      // (scale,shift): t:[0,64) y:[64,128) u2:[128,384) usc:[384,640)

// ---------------- small kernels ----------------
__global__ void zero_kernel() {
    int i = blockIdx.x * blockDim.x + threadIdx.x;
    if (i < NPTS) g_cnt[i] = 0;
    if (i < 1280) g_stats[i] = 0.0;
}

__global__ void scatter_kernel(const int* __restrict__ e_ref,
                               const int* __restrict__ e_qry, int E) {
    int e = blockIdx.x * blockDim.x + threadIdx.x;
    if (e >= E) return;
    int q = e_qry[e];
    int r = e_ref[e];
    int slot = atomicAdd(&g_cnt[q], 1);
    if (slot < CAP) g_nbr[(size_t)q * CAP + slot] = r;
}

__device__ __forceinline__ void bsplit(float v, __nv_bfloat16& h, __nv_bfloat16& l) {
    h = __float2bfloat16(v);
    l = __float2bfloat16(v - __bfloat162float(h));
}

// W [K, N] fp32 -> out [N, 2K] bf16 (hi | lo)
__global__ void wsplit_kernel(const float* __restrict__ W, __nv_bfloat16* __restrict__ out,
                              int K, int N) {
    int i = blockIdx.x * blockDim.x + threadIdx.x;
    if (i >= K * N) return;
    int k = i / N, n = i % N;
    __nv_bfloat16 h, l;
    bsplit(W[i], h, l);
    out[(size_t)n * 2 * K + k] = h;
    out[(size_t)n * 2 * K + K + k] = l;
}

__global__ void bn_prep(int statOff, int C, const float* __restrict__ g,
                        const float* __restrict__ b, int prepOff, int M) {
    int i = threadIdx.x;
    if (i >= C) return;
    double m = g_stats[statOff + i] / (double)M;
    double v = g_stats[statOff + C + i] / (double)M - m * m;
    float rstd = rsqrtf((float)v + EPSBN);
    float scale = g[i] * rstd;
    float shift = b[i] - (float)m * scale;
    g_bnp[prepOff + i] = make_float2(scale, shift);
}

// ---------------- S build: serial per-warp loop (proven), BN+leaky fused ----------------
__global__ __launch_bounds__(256) void sbuild_kernel(
    const float* __restrict__ pos, const float* __restrict__ kp)
{
    __shared__ float skp[45];
    int tid = threadIdx.x;
    int lane = tid & 31;
    int warp = tid >> 5;
    if (tid < 45) skp[tid] = kp[tid];
    __syncthreads();

    int q = blockIdx.x * 8 + warp;
    if (q >= NPTS) return;

    float kx = 0.f, ky = 0.f, kz = 0.f;
    if (lane < KPTS) {
        kx = skp[lane * 3 + 0];
        ky = skp[lane * 3 + 1];
        kz = skp[lane * 3 + 2];
    }
    float2 p0 = __ldg(&g_bnp[2 * lane]);
    float2 p1 = __ldg(&g_bnp[2 * lane + 1]);

    float a0[KPTS], a1[KPTS];
#pragma unroll
    for (int k = 0; k < KPTS; ++k) { a0[k] = 0.f; a1[k] = 0.f; }

    float4 pq = __ldg((const float4*)pos + q);
    int cnt = g_cnt[q];
    if (cnt > CAP) cnt = CAP;
    const int* nb = g_nbr + (size_t)q * CAP;

    for (int j = 0; j < cnt; ++j) {
        int r = __ldg(&nb[j]);
        float4 pr = __ldg((const float4*)pos + r);
        float rx = pr.y - pq.y;
        float ry = pr.z - pq.z;
        float rz = pr.w - pq.w;
        float infl = 0.f;
        if (lane < KPTS) {
            float dx = rx - kx, dy = ry - ky, dz = rz - kz;
            float d2 = dx * dx + dy * dy + dz * dz;
            if (d2 < SIGMA * SIGMA)
                infl = 1.f - sqrtf(d2) * (1.f / SIGMA);
        }
        unsigned m = __ballot_sync(0xffffffffu, infl > 0.f);
        if (!m) continue;
        float2 hv = __ldg((const float2*)g_t + (size_t)r * 32 + lane);
        float h0 = fmaf(hv.x, p0.x, p0.y);
        h0 = (h0 >= 0.f) ? h0 : NEG * h0;
        float h1 = fmaf(hv.y, p1.x, p1.y);
        h1 = (h1 >= 0.f) ? h1 : NEG * h1;
#pragma unroll
        for (int k = 0; k < KPTS; ++k) {
            if (m & (1u << k)) {
                float w = __shfl_sync(0xffffffffu, infl, k);
                a0[k] += w * h0;
                a1[k] += w * h1;
            }
        }
    }

    __nv_bfloat162* Sout = (__nv_bfloat162*)(g_Sb + (size_t)q * 1920);
#pragma unroll
    for (int k = 0; k < KPTS; ++k) {
        __nv_bfloat16 h0, l0, h1, l1;
        bsplit(a0[k], h0, l0);
        bsplit(a1[k], h1, l1);
        __nv_bfloat162 hh; hh.x = h0; hh.y = h1;
        __nv_bfloat162 ll; ll.x = l0; ll.y = l1;
        Sout[k * 32 + lane] = hh;
        Sout[480 + k * 32 + lane] = ll;
    }
}

// ---------------- shared MMA helper ----------------
__device__ __forceinline__ void mma16816(float* c, const uint32_t* a, const uint32_t* b) {
    asm volatile(
        "mma.sync.aligned.m16n8k16.row.col.f32.bf16.bf16.f32 "
        "{%0,%1,%2,%3}, {%4,%5,%6,%7}, {%8,%9}, {%0,%1,%2,%3};"
        : "+f"(c[0]), "+f"(c[1]), "+f"(c[2]), "+f"(c[3])
        : "r"(a[0]), "r"(a[1]), "r"(a[2]), "r"(a[3]), "r"(b[0]), "r"(b[1]));
}

#define ROWP 72
#define SECA (128 * ROWP)   // bf16 elems per A section
#define SECB (64 * ROWP)    // bf16 elems per B section

// ---------------- gemm_mma (chunked-K, presplit A) — unchanged, used only for S ----------------
#define A_SEC (128 * ROWP)
#define B_SEC (64 * ROWP)
#define GSMEM_BYTES ((2 * A_SEC + 2 * B_SEC) * 2 + 512)

__global__ __launch_bounds__(256) void gemm_mma(
    const __nv_bfloat16* __restrict__ A,
    const __nv_bfloat16* __restrict__ B,
    float* __restrict__ C,
    int M, int K, int Nc, int statOff, int statC)
{
    extern __shared__ char smem[];
    __nv_bfloat16* sA = (__nv_bfloat16*)smem;
    __nv_bfloat16* sB = sA + 2 * A_SEC;
    float* red = (float*)(smem + (2 * A_SEC + 2 * B_SEC) * 2);

    const int tid = threadIdx.x;
    const int lane = tid & 31;
    const int wid = tid >> 5;
    const int wm = wid & 3;
    const int wn = wid >> 2;
    const int g = lane >> 2;
    const int t = lane & 3;
    const int m0 = blockIdx.x * 128;
    const int n0 = blockIdx.y * 64;
    const int lda = 2 * K;
    const int nch = K >> 6;

    if (tid < 128) red[tid] = 0.f;

    float acc[2][4][4];
#pragma unroll
    for (int mi = 0; mi < 2; ++mi)
#pragma unroll
        for (int ni = 0; ni < 4; ++ni)
#pragma unroll
            for (int j = 0; j < 4; ++j) acc[mi][ni][j] = 0.f;

    for (int c = 0; c < nch; ++c) {
        int koh = c * 64;
#pragma unroll
        for (int i = 0; i < 4; ++i) {
            int idx = tid + 256 * i;
            int r = idx >> 3, cw = idx & 7;
            int gr = m0 + r;
            uint4 vh = make_uint4(0, 0, 0, 0), vl = vh;
            if (gr < M) {
                const uint4* base = (const uint4*)(A + (size_t)gr * lda);
                vh = __ldg(base + (koh >> 3) + cw);
                vl = __ldg(base + ((K + koh) >> 3) + cw);
            }
            *(uint4*)(sA + r * ROWP + cw * 8) = vh;
            *(uint4*)(sA + A_SEC + r * ROWP + cw * 8) = vl;
        }
#pragma unroll
        for (int i = 0; i < 2; ++i) {
            int idx = tid + 256 * i;
            int r = idx >> 3, cw = idx & 7;
            const uint4* base = (const uint4*)(B + (size_t)(n0 + r) * lda);
            uint4 vh = __ldg(base + (koh >> 3) + cw);
            uint4 vl = __ldg(base + ((K + koh) >> 3) + cw);
            *(uint4*)(sB + r * ROWP + cw * 8) = vh;
            *(uint4*)(sB + B_SEC + r * ROWP + cw * 8) = vl;
        }
        __syncthreads();

#pragma unroll
        for (int ks = 0; ks < 4; ++ks) {
            int col = ks * 16 + 2 * t;
            uint32_t ah[2][4], al[2][4];
#pragma unroll
            for (int mi = 0; mi < 2; ++mi) {
                const __nv_bfloat16* p = sA + (wm * 32 + mi * 16 + g) * ROWP + col;
                ah[mi][0] = *(const uint32_t*)p;
                ah[mi][1] = *(const uint32_t*)(p + 8 * ROWP);
                ah[mi][2] = *(const uint32_t*)(p + 8);
                ah[mi][3] = *(const uint32_t*)(p + 8 * ROWP + 8);
                const __nv_bfloat16* qp = p + A_SEC;
                al[mi][0] = *(const uint32_t*)qp;
                al[mi][1] = *(const uint32_t*)(qp + 8 * ROWP);
                al[mi][2] = *(const uint32_t*)(qp + 8);
                al[mi][3] = *(const uint32_t*)(qp + 8 * ROWP + 8);
            }
            uint32_t bh[4][2], bl[4][2];
#pragma unroll
            for (int ni = 0; ni < 4; ++ni) {
                const __nv_bfloat16* p = sB + (wn * 32 + ni * 8 + g) * ROWP + col;
                bh[ni][0] = *(const uint32_t*)p;
                bh[ni][1] = *(const uint32_t*)(p + 8);
                const __nv_bfloat16* qp = p + B_SEC;
                bl[ni][0] = *(const uint32_t*)qp;
                bl[ni][1] = *(const uint32_t*)(qp + 8);
            }
#pragma unroll
            for (int mi = 0; mi < 2; ++mi)
#pragma unroll
                for (int ni = 0; ni < 4; ++ni) {
                    mma16816(acc[mi][ni], ah[mi], bh[ni]);
                    mma16816(acc[mi][ni], ah[mi], bl[ni]);
                    mma16816(acc[mi][ni], al[mi], bh[ni]);
                }
        }
        __syncthreads();
    }

#pragma unroll
    for (int ni = 0; ni < 4; ++ni) {
        int colL = wn * 32 + ni * 8 + 2 * t;
        float s0 = 0.f, q0 = 0.f, s1 = 0.f, q1 = 0.f;
#pragma unroll
        for (int mi = 0; mi < 2; ++mi) {
            float* f = acc[mi][ni];
            int row = m0 + wm * 32 + mi * 16 + g;
            if (row < M) {
                C[(size_t)row * Nc + n0 + colL] = f[0];
                C[(size_t)row * Nc + n0 + colL + 1] = f[1];
                s0 += f[0]; q0 += f[0] * f[0];
                s1 += f[1]; q1 += f[1] * f[1];
            }
            if (row + 8 < M) {
                C[(size_t)(row + 8) * Nc + n0 + colL] = f[2];
                C[(size_t)(row + 8) * Nc + n0 + colL + 1] = f[3];
                s0 += f[2]; q0 += f[2] * f[2];
                s1 += f[3]; q1 += f[3] * f[3];
            }
        }
#pragma unroll
        for (int off = 4; off < 32; off <<= 1) {
            s0 += __shfl_xor_sync(0xffffffffu, s0, off);
            q0 += __shfl_xor_sync(0xffffffffu, q0, off);
            s1 += __shfl_xor_sync(0xffffffffu, s1, off);
            q1 += __shfl_xor_sync(0xffffffffu, q1, off);
        }
        if (g == 0) {
            atomicAdd(&red[colL], s0);
            atomicAdd(&red[64 + colL], q0);
            atomicAdd(&red[colL + 1], s1);
            atomicAdd(&red[64 + colL + 1], q1);
        }
    }
    __syncthreads();
    if (tid < 64) {
        atomicAdd(&g_stats[statOff + n0 + tid], (double)red[tid]);
        atomicAdd(&g_stats[statOff + statC + n0 + tid], (double)red[64 + tid]);
    }
}

// ---------------- gemm_wide: fp32 A staged once with inline split (+BN for AMODE 2),
// loops over all 64-wide N tiles. For K <= 128 GEMMs (t, u2, usc). ----------------
// AMODE 1: A fp32, plain hi/lo split.  AMODE 2: A fp32, BN(scale,shift)+leaky then split.
template <int AMODE>
__global__ __launch_bounds__(256) void gemm_wide(
    const float* __restrict__ A32,
    const __nv_bfloat16* __restrict__ B,
    float* __restrict__ C,
    int M, int K, int Nc, int statOff, int prepOff)
{
    extern __shared__ char smem[];
    const int nch = K >> 6;
    const int ntiles = Nc >> 6;
    __nv_bfloat16* sA = (__nv_bfloat16*)smem;                      // 2*nch sections of SECA
    __nv_bfloat16* sB = sA + 2 * nch * SECA;                       // 2*nch sections of SECB
    float* red = (float*)(sB + 2 * nch * SECB);

    const int tid = threadIdx.x;
    const int lane = tid & 31;
    const int wid = tid >> 5;
    const int wm = wid & 3;
    const int wn = wid >> 2;
    const int g = lane >> 2;
    const int t = lane & 3;
    const int m0 = blockIdx.x * 128;
    const int ldb = 2 * K;

    // ---- stage whole A panel with inline conversion ----
    for (int c = 0; c < nch; ++c) {
        __nv_bfloat16* dAh = sA + (2 * c) * SECA;
        __nv_bfloat16* dAl = dAh + SECA;
        int koh = c * 64;
#pragma unroll
        for (int i = 0; i < 8; ++i) {
            int idx = tid + 256 * i;
            int r = idx >> 4;
            int cc = (idx & 15) * 4;
            int gr = m0 + r;
            float4 v = make_float4(0.f, 0.f, 0.f, 0.f);
            if (gr < M)
                v = __ldg((const float4*)(A32 + (size_t)gr * K + koh + cc));
            __nv_bfloat16 h[4], l[4];
#pragma unroll
            for (int j = 0; j < 4; ++j) {
                float u = (&v.x)[j];
                if (AMODE == 2) {
                    float2 p = __ldg(&g_bnp[prepOff + koh + cc + j]);
                    u = fmaf(u, p.x, p.y);
                    u = (u >= 0.f) ? u : NEG * u;
                }
                bsplit(u, h[j], l[j]);
            }
            __nv_bfloat162 h01, h23, l01, l23;
            h01.x = h[0]; h01.y = h[1]; h23.x = h[2]; h23.y = h[3];
            l01.x = l[0]; l01.y = l[1]; l23.x = l[2]; l23.y = l[3];
            uint2 hp, lp;
            hp.x = *(uint32_t*)&h01; hp.y = *(uint32_t*)&h23;
            lp.x = *(uint32_t*)&l01; lp.y = *(uint32_t*)&l23;
            *(uint2*)(dAh + r * ROWP + cc) = hp;
            *(uint2*)(dAl + r * ROWP + cc) = lp;
        }
    }

    // ---- loop over 64-wide N tiles ----
    for (int nt = 0; nt < ntiles; ++nt) {
        int n0 = nt * 64;
        if (tid < 128) red[tid] = 0.f;
        // stage B tile (all K chunks)
        for (int c = 0; c < nch; ++c) {
            __nv_bfloat16* dBh = sB + (2 * c) * SECB;
            __nv_bfloat16* dBl = dBh + SECB;
            int koh = c * 64;
#pragma unroll
            for (int i = 0; i < 2; ++i) {
                int idx = tid + 256 * i;
                int r = idx >> 3, cw = idx & 7;
                const uint4* base = (const uint4*)(B + (size_t)(n0 + r) * ldb);
                uint4 vh = __ldg(base + (koh >> 3) + cw);
                uint4 vl = __ldg(base + ((K + koh) >> 3) + cw);
                *(uint4*)(dBh + r * ROWP + cw * 8) = vh;
                *(uint4*)(dBl + r * ROWP + cw * 8) = vl;
            }
        }
        __syncthreads();

        float acc[2][4][4];
#pragma unroll
        for (int mi = 0; mi < 2; ++mi)
#pragma unroll
            for (int ni = 0; ni < 4; ++ni)
#pragma unroll
                for (int j = 0; j < 4; ++j) acc[mi][ni][j] = 0.f;

        for (int c = 0; c < nch; ++c) {
            const __nv_bfloat16* pAh = sA + (2 * c) * SECA;
            const __nv_bfloat16* pAl = pAh + SECA;
            const __nv_bfloat16* pBh = sB + (2 * c) * SECB;
            const __nv_bfloat16* pBl = pBh + SECB;
#pragma unroll
            for (int ks = 0; ks < 4; ++ks) {
                int col = ks * 16 + 2 * t;
                uint32_t ah[2][4], al[2][4];
#pragma unroll
                for (int mi = 0; mi < 2; ++mi) {
                    const __nv_bfloat16* p = pAh + (wm * 32 + mi * 16 + g) * ROWP + col;
                    ah[mi][0] = *(const uint32_t*)p;
                    ah[mi][1] = *(const uint32_t*)(p + 8 * ROWP);
                    ah[mi][2] = *(const uint32_t*)(p + 8);
                    ah[mi][3] = *(const uint32_t*)(p + 8 * ROWP + 8);
                    const __nv_bfloat16* qp = pAl + (wm * 32 + mi * 16 + g) * ROWP + col;
                    al[mi][0] = *(const uint32_t*)qp;
                    al[mi][1] = *(const uint32_t*)(qp + 8 * ROWP);
                    al[mi][2] = *(const uint32_t*)(qp + 8);
                    al[mi][3] = *(const uint32_t*)(qp + 8 * ROWP + 8);
                }
                uint32_t bh[4][2], bl[4][2];
#pragma unroll
                for (int ni = 0; ni < 4; ++ni) {
                    const __nv_bfloat16* p = pBh + (wn * 32 + ni * 8 + g) * ROWP + col;
                    bh[ni][0] = *(const uint32_t*)p;
                    bh[ni][1] = *(const uint32_t*)(p + 8);
                    const __nv_bfloat16* qp = pBl + (wn * 32 + ni * 8 + g) * ROWP + col;
                    bl[ni][0] = *(const uint32_t*)qp;
                    bl[ni][1] = *(const uint32_t*)(qp + 8);
                }
#pragma unroll
                for (int mi = 0; mi < 2; ++mi)
#pragma unroll
                    for (int ni = 0; ni < 4; ++ni) {
                        mma16816(acc[mi][ni], ah[mi], bh[ni]);
                        mma16816(acc[mi][ni], ah[mi], bl[ni]);
                        mma16816(acc[mi][ni], al[mi], bh[ni]);
                    }
            }
        }

        // epilogue for this tile
#pragma unroll
        for (int ni = 0; ni < 4; ++ni) {
            int colL = wn * 32 + ni * 8 + 2 * t;
            float s0 = 0.f, q0 = 0.f, s1 = 0.f, q1 = 0.f;
#pragma unroll
            for (int mi = 0; mi < 2; ++mi) {
                float* f = acc[mi][ni];
                int row = m0 + wm * 32 + mi * 16 + g;
                if (row < M) {
                    C[(size_t)row * Nc + n0 + colL] = f[0];
                    C[(size_t)row * Nc + n0 + colL + 1] = f[1];
                    s0 += f[0]; q0 += f[0] * f[0];
                    s1 += f[1]; q1 += f[1] * f[1];
                }
                if (row + 8 < M) {
                    C[(size_t)(row + 8) * Nc + n0 + colL] = f[2];
                    C[(size_t)(row + 8) * Nc + n0 + colL + 1] = f[3];
                    s0 += f[2]; q0 += f[2] * f[2];
                    s1 += f[3]; q1 += f[3] * f[3];
                }
            }
#pragma unroll
            for (int off = 4; off < 32; off <<= 1) {
                s0 += __shfl_xor_sync(0xffffffffu, s0, off);
                q0 += __shfl_xor_sync(0xffffffffu, q0, off);
                s1 += __shfl_xor_sync(0xffffffffu, s1, off);
                q1 += __shfl_xor_sync(0xffffffffu, q1, off);
            }
            if (g == 0) {
                atomicAdd(&red[colL], s0);
                atomicAdd(&red[64 + colL], q0);
                atomicAdd(&red[colL + 1], s1);
                atomicAdd(&red[64 + colL + 1], q1);
            }
        }
        __syncthreads();
        if (tid < 64) {
            atomicAdd(&g_stats[statOff + n0 + tid], (double)red[tid]);
            atomicAdd(&g_stats[statOff + Nc + n0 + tid], (double)red[64 + tid]);
        }
        __syncthreads();   // before next tile overwrites sB / red
    }
}

// ---------------- final: out = leaky(bn(u2)) + bn(usc), float4 ----------------
__global__ void final_kernel(float4* __restrict__ out, int n4) {
    int i = blockIdx.x * blockDim.x + threadIdx.x;
    if (i >= n4) return;
    int c4 = (i & 63) * 4;
    float4 a = __ldg((const float4*)g_u2 + i);
    float4 s = __ldg((const float4*)g_usc + i);
    float4 o;
#pragma unroll
    for (int j = 0; j < 4; ++j) {
        float2 p2 = __ldg(&g_bnp[128 + c4 + j]);
        float2 ps = __ldg(&g_bnp[384 + c4 + j]);
        float u = fmaf((&a.x)[j], p2.x, p2.y);
        u = (u >= 0.f) ? u : NEG * u;
        (&o.x)[j] = u + fmaf((&s.x)[j], ps.x, ps.y);
    }
    out[i] = o;
}

// ---------------- launch ----------------
extern "C" void kernel_launch(void* const* d_in, const int* in_sizes, int n_in,
                              void* d_out, int out_size) {
    const float* pos    = (const float*)d_in[0];
    const float* x      = (const float*)d_in[1];
    const int*   e_ref  = (const int*)  d_in[2];
    const int*   e_qry  = (const int*)  d_in[3];
    const float* W1     = (const float*)d_in[4];
    const float* g1     = (const float*)d_in[5];
    const float* b1     = (const float*)d_in[6];
    const float* kp     = (const float*)d_in[7];
    const float* Wkp    = (const float*)d_in[8];
    const float* gkp    = (const float*)d_in[9];
    const float* bkp    = (const float*)d_in[10];
    const float* W2     = (const float*)d_in[11];
    const float* g2     = (const float*)d_in[12];
    const float* b2     = (const float*)d_in[13];
    const float* Wsc    = (const float*)d_in[14];
    const float* gsc    = (const float*)d_in[15];
    const float* bsc    = (const float*)d_in[16];
    float* out = (float*)d_out;

    const int M = NPTS;
    const int E = in_sizes[2];

    float *t_p, *u2_p, *usc_p;
    __nv_bfloat16 *Sb_p, *w1b_p, *wkpb_p, *w2b_p, *wscb_p;
    cudaGetSymbolAddress((void**)&t_p,    g_t);
    cudaGetSymbolAddress((void**)&u2_p,   g_u2);
    cudaGetSymbolAddress((void**)&usc_p,  g_usc);
    cudaGetSymbolAddress((void**)&Sb_p,   g_Sb);
    cudaGetSymbolAddress((void**)&w1b_p,  g_w1b);
    cudaGetSymbolAddress((void**)&wkpb_p, g_wkpb);
    cudaGetSymbolAddress((void**)&w2b_p,  g_w2b);
    cudaGetSymbolAddress((void**)&wscb_p, g_wscb);

    cudaFuncSetAttribute(gemm_mma, cudaFuncAttributeMaxDynamicSharedMemorySize, GSMEM_BYTES);
    // gemm_wide smem: (2*nch)*(SECA+SECB)*2 bytes + 512; K=128 worst case
    const int GW_SMEM_K128 = 4 * (SECA + SECB) * 2 + 512;   // 111104
    const int GW_SMEM_K64  = 2 * (SECA + SECB) * 2 + 512;   // 55808
    cudaFuncSetAttribute(gemm_wide<1>, cudaFuncAttributeMaxDynamicSharedMemorySize, GW_SMEM_K128);
    cudaFuncSetAttribute(gemm_wide<2>, cudaFuncAttributeMaxDynamicSharedMemorySize, GW_SMEM_K128);

    // 0. zero counters + stats; bin edges
    zero_kernel<<<(NPTS + 255) / 256, 256>>>();
    scatter_kernel<<<(E + 255) / 256, 256>>>(e_ref, e_qry, E);

    // weight conversions (small)
    wsplit_kernel<<<(DIN * D2 + 255) / 256, 256>>>(W1, w1b_p, DIN, D2);
    wsplit_kernel<<<(KPTS * D2 * D2 + 255) / 256, 256>>>(Wkp, wkpb_p, KPTS * D2, D2);
    wsplit_kernel<<<(D2 * DOUT + 255) / 256, 256>>>(W2, w2b_p, D2, DOUT);
    wsplit_kernel<<<(DIN * DOUT + 255) / 256, 256>>>(Wsc, wscb_p, DIN, DOUT);

    const int MB = (M + 127) / 128;
    int n4_256 = M * DOUT / 4;

    // 1. t = x @ W1   (fp32 A inline-split; K=128, Nc=64, stats @0)
    gemm_wide<1><<<MB, 256, GW_SMEM_K128>>>(x, w1b_p, t_p, M, DIN, D2, 0, 0);
    // 2. BN params for t
    bn_prep<<<1, 64>>>(0, D2, g1, b1, 0, M);
    // 3. build split-bf16 S (BN+leaky fused into the gather)
    sbuild_kernel<<<(M + 7) / 8, 256>>>(pos, kp);
    // 4. y = S @ Wkp  (K=960, Nc=64, stats @128) -> g_t
    gemm_mma<<<dim3(MB, 1), 256, GSMEM_BYTES>>>(Sb_p, wkpb_p, t_p, M, KPTS * D2, D2, 128, D2);
    // 5. BN params for y
    bn_prep<<<1, 64>>>(128, D2, gkp, bkp, 64, M);
    // 6. u2 = leaky(bn(y)) @ W2  (BN+leaky fused into A staging; K=64, Nc=256, stats @256)
    gemm_wide<2><<<MB, 256, GW_SMEM_K64>>>(t_p, w2b_p, u2_p, M, D2, DOUT, 256, 64);
    // 7. usc = x @ Wsc  (K=128, Nc=256, stats @768)
    gemm_wide<1><<<MB, 256, GW_SMEM_K128>>>(x, wscb_p, usc_p, M, DIN, DOUT, 768, 0);
    // 8. output
    bn_prep<<<1, 256>>>(256, DOUT, g2, b2, 128, M);
    bn_prep<<<1, 256>>>(768, DOUT, gsc, bsc, 384, M);
    final_kernel<<<(n4_256 + 255) / 256, 256>>>((float4*)out, n4_256);
}